// round 1
// baseline (speedup 1.0000x reference)
#include <cuda_runtime.h>
#include <math.h>
#include <stdint.h>

// ---------------- problem constants ----------------
#define T_DIM 256
#define B_DIM 256
#define D_DIM 128
#define H_DIM 512
#define G3H   1536            // 3*H
#define TM1   255             // T-1
#define K10D  1280            // 10*D
#define PRE_ROWS (B_DIM*TM1)  // 65280
#define PRED_ELEMS (PRE_ROWS*D_DIM)  // 8355840

// ---------------- scratch (static device allocations; no cudaMalloc allowed) --
__device__ float g_xw[(size_t)T_DIM * B_DIM * G3H];       // (t,b,3H)  402MB
__device__ float g_hidden[(size_t)B_DIM * T_DIM * H_DIM]; // (b,t,H)   134MB
__device__ float g_pre[(size_t)PRE_ROWS * K10D];          // (b,t,10D) 334MB
__device__ float g_td[PRE_ROWS];                          // (b,t)
__device__ float g_h[2 * B_DIM * H_DIM];                  // double-buffered h

// =======================================================================
// Generic 128x128 fp32 GEMM, C[M,N] = A[M,K] * B[N,K]^T (+ epilogue)
// MODE 0: xw     : epi c += bias[n]
// MODE 1: pre    : A-rows remapped into g_hidden (skip t=255);
//                  epi c = sigmoid(c + td[row]*w1last[n*513] + bias[n])
// MODE 2: preds  : epi c = (t < lengths[b]-1) ? c + bias[n] : 0
// M must be a multiple of 128, N a multiple of 128. K arbitrary (guarded).
// =======================================================================
template <int MODE>
__global__ __launch_bounds__(256)
void gemm128(const float* __restrict__ A, const float* __restrict__ B,
             float* __restrict__ C,
             int M, int N, int K, int lda, int ldb, int ldc,
             const float* __restrict__ bias,
             const float* __restrict__ td,
             const float* __restrict__ w1last,
             const int* __restrict__ lengths)
{
    __shared__ __align__(16) float As[8][128];
    __shared__ __align__(16) float Bs[8][128];

    const int tid = threadIdx.x;
    const int row0 = blockIdx.y * 128;
    const int col0 = blockIdx.x * 128;
    const int tx = tid & 15;       // 0..15  -> cols tx*8..tx*8+7
    const int ty = tid >> 4;       // 0..15  -> rows ty*8..ty*8+7

    // precompute load offsets (constant over the k loop)
    int lr[4], lk[4];
    size_t aoff[4], boff[4];
#pragma unroll
    for (int i = 0; i < 4; i++) {
        int lin = tid + i * 256;       // 0..1023 covers 128 rows x 8 k
        lr[i] = lin >> 3;
        lk[i] = lin & 7;
        int grow = row0 + lr[i];
        int arow = grow;
        if (MODE == 1) {               // row -> (b, t) with t<255, hidden has T=256 rows per b
            int b_ = grow / 255;
            int t_ = grow - b_ * 255;
            arow = b_ * 256 + t_;
        }
        aoff[i] = (size_t)arow * lda + lk[i];
        boff[i] = (size_t)(col0 + lr[i]) * ldb + lk[i];
    }

    float acc[8][8];
#pragma unroll
    for (int i = 0; i < 8; i++)
#pragma unroll
        for (int j = 0; j < 8; j++) acc[i][j] = 0.f;

    for (int k0 = 0; k0 < K; k0 += 8) {
#pragma unroll
        for (int i = 0; i < 4; i++) {
            int gk = k0 + lk[i];
            As[lk[i]][lr[i]] = (gk < K) ? A[aoff[i] + k0] : 0.f;
            Bs[lk[i]][lr[i]] = (gk < K) ? B[boff[i] + k0] : 0.f;
        }
        __syncthreads();
#pragma unroll
        for (int kk = 0; kk < 8; kk++) {
            float ar[8], br[8];
            *(float4*)&ar[0] = *(const float4*)&As[kk][ty * 8];
            *(float4*)&ar[4] = *(const float4*)&As[kk][ty * 8 + 4];
            *(float4*)&br[0] = *(const float4*)&Bs[kk][tx * 8];
            *(float4*)&br[4] = *(const float4*)&Bs[kk][tx * 8 + 4];
#pragma unroll
            for (int i = 0; i < 8; i++)
#pragma unroll
                for (int j = 0; j < 8; j++) acc[i][j] += ar[i] * br[j];
        }
        __syncthreads();
    }

    // epilogue
#pragma unroll
    for (int i = 0; i < 8; i++) {
        int grow = row0 + ty * 8 + i;
        float tdv = 0.f;
        int b_ = 0, t_ = 0;
        if (MODE == 1) tdv = td[grow];
        if (MODE == 2) { b_ = grow / 255; t_ = grow - b_ * 255; }
#pragma unroll
        for (int j = 0; j < 8; j++) {
            int gcol = col0 + tx * 8 + j;
            float v = acc[i][j];
            if (MODE == 0) {
                v += bias[gcol];
            } else if (MODE == 1) {
                v += bias[gcol] + tdv * w1last[(size_t)gcol * 513];
                v = 1.f / (1.f + expf(-v));
            } else { // MODE 2
                v = (t_ < lengths[b_] - 1) ? (v + bias[gcol]) : 0.f;
            }
            C[(size_t)grow * ldc + gcol] = v;
        }
    }
}

// =======================================================================
// GRU step kernel: one time step.  grid = (16 batch-groups, 8 H-chunks),
// 128 threads.  Each CTA: 16 batch rows x 64 H-units (x 3 gates), K=512.
// Thread tile: 1 j x 8 b x 3 gates.  w_hh k-tiles register-prefetched.
// =======================================================================
__global__ __launch_bounds__(128)
void gru_step(const float* __restrict__ hin, float* __restrict__ hout,
              const float* __restrict__ xw,     // g_xw base
              const float* __restrict__ w_hh, const float* __restrict__ b_hh,
              const int* __restrict__ lengths,
              float* __restrict__ hidden,       // g_hidden base
              int t)
{
    __shared__ float h_s[512][17];     // [k][b] padded, 34816B
    __shared__ float w_s[3][64][17];   // [gate][j][kk] padded, 13056B

    const int tid = threadIdx.x;       // 128 threads
    const int bg  = blockIdx.x;        // 0..15 batch group
    const int ch  = blockIdx.y;        // 0..7  H chunk
    const int j   = tid & 63;          // 0..63
    const int bh  = tid >> 6;          // 0..1  (8 batch rows each)
    const int jg  = ch * 64 + j;       // global H unit

    // load h (16 x 512) into SMEM, transposed [k][b], float4 global loads
#pragma unroll
    for (int i = 0; i < 16; i++) {
        int lin = tid + i * 128;       // 0..2047 quads
        int b   = lin >> 7;            // 0..15
        int kq  = lin & 127;
        float4 h4 = *(const float4*)&hin[(size_t)(bg * 16 + b) * H_DIM + (kq << 2)];
        h_s[kq * 4 + 0][b] = h4.x;
        h_s[kq * 4 + 1][b] = h4.y;
        h_s[kq * 4 + 2][b] = h4.z;
        h_s[kq * 4 + 3][b] = h4.w;
    }

    float acc[3][8];
#pragma unroll
    for (int g = 0; g < 3; g++)
#pragma unroll
        for (int bb = 0; bb < 8; bb++) acc[g][bb] = 0.f;

    // w tile prefetch into registers: 192 rows x 16 k = 768 float4, 6/thread
    float4 wreg[6];
    int wrl[6], wkq[6];
    size_t wbase[6];
#pragma unroll
    for (int i = 0; i < 6; i++) {
        int lin = tid + i * 128;       // 0..767
        int rl  = lin >> 2;            // 0..191
        int kq  = lin & 3;
        int g   = rl >> 6;
        int jr  = rl & 63;
        wrl[i] = rl; wkq[i] = kq;
        wbase[i] = (size_t)(g * H_DIM + ch * 64 + jr) * H_DIM + (kq << 2);
        wreg[i] = *(const float4*)&w_hh[wbase[i]];   // tile k0=0
    }
    __syncthreads();   // h_s ready

    for (int k0 = 0; k0 < 512; k0 += 16) {
#pragma unroll
        for (int i = 0; i < 6; i++) {
            int g  = wrl[i] >> 6;
            int jr = wrl[i] & 63;
            int kb = wkq[i] * 4;
            w_s[g][jr][kb + 0] = wreg[i].x;
            w_s[g][jr][kb + 1] = wreg[i].y;
            w_s[g][jr][kb + 2] = wreg[i].z;
            w_s[g][jr][kb + 3] = wreg[i].w;
        }
        __syncthreads();
        if (k0 + 16 < 512) {
#pragma unroll
            for (int i = 0; i < 6; i++)
                wreg[i] = *(const float4*)&w_hh[wbase[i] + k0 + 16];
        }
#pragma unroll
        for (int kk = 0; kk < 16; kk++) {
            float w0 = w_s[0][j][kk];
            float w1v = w_s[1][j][kk];
            float w2v = w_s[2][j][kk];
#pragma unroll
            for (int bb = 0; bb < 8; bb++) {
                float hv = h_s[k0 + kk][bh * 8 + bb];
                acc[0][bb] += w0 * hv;
                acc[1][bb] += w1v * hv;
                acc[2][bb] += w2v * hv;
            }
        }
        __syncthreads();
    }

    const float bhr = b_hh[jg];
    const float bhz = b_hh[H_DIM + jg];
    const float bhn = b_hh[2 * H_DIM + jg];

#pragma unroll
    for (int bb = 0; bb < 8; bb++) {
        int bl = bh * 8 + bb;
        int bglob = bg * 16 + bl;
        const float* xwp = xw + ((size_t)t * B_DIM + bglob) * G3H;
        float xr = xwp[jg];
        float xz = xwp[H_DIM + jg];
        float xn = xwp[2 * H_DIM + jg];
        float r = 1.f / (1.f + expf(-(xr + acc[0][bb] + bhr)));
        float z = 1.f / (1.f + expf(-(xz + acc[1][bb] + bhz)));
        float n = tanhf(xn + r * (acc[2][bb] + bhn));
        float hold = h_s[jg][bl];
        float hnew = (1.f - z) * n + z * hold;
        bool valid = (t < lengths[bglob]);
        hout[(size_t)bglob * H_DIM + jg] = valid ? hnew : hold;
        hidden[((size_t)bglob * T_DIM + t) * H_DIM + jg] = valid ? hnew : 0.f;
    }
}

// =======================================================================
// td[b,t] = x[t+1,b,0] - x[t,b,0]   for t in [0,255)
// =======================================================================
__global__ void td_kernel(const float* __restrict__ x, float* __restrict__ td)
{
    int i = blockIdx.x * 256 + threadIdx.x;    // 65280 total
    if (i < PRE_ROWS) {
        int b = i / 255;
        int t = i - b * 255;
        td[i] = x[(size_t)((t + 1) * B_DIM + b) * (D_DIM + 1)]
              - x[(size_t)(t * B_DIM + b) * (D_DIM + 1)];
    }
}

// =======================================================================
// dist_params[b,p] = exp(-(h_last[b] . wp[p] + bp[p]));  also emit lengths
// one block per b, 3 warps (one per p)
// =======================================================================
__global__ void tail_kernel(const float* __restrict__ hlast,
                            const float* __restrict__ wp,
                            const float* __restrict__ bp,
                            const int* __restrict__ lengths,
                            float* __restrict__ out)
{
    int b = blockIdx.x;
    int w = threadIdx.x >> 5;      // 0..2
    int lane = threadIdx.x & 31;
    float s = 0.f;
    for (int k = lane; k < H_DIM; k += 32)
        s += hlast[(size_t)b * H_DIM + k] * wp[(size_t)w * H_DIM + k];
#pragma unroll
    for (int o = 16; o; o >>= 1) s += __shfl_xor_sync(0xffffffffu, s, o);
    if (lane == 0)
        out[PRED_ELEMS + b * 3 + w] = expf(-(s + bp[w]));
    if (threadIdx.x == 0)
        out[PRED_ELEMS + B_DIM * 3 + b] = (float)lengths[b];
}

// =======================================================================
// host launcher
// =======================================================================
extern "C" void kernel_launch(void* const* d_in, const int* in_sizes, int n_in,
                              void* d_out, int out_size)
{
    const float* x      = (const float*)d_in[0];
    const float* h0     = (const float*)d_in[1];
    const int*   lens   = (const int*)  d_in[2];
    const float* w_ih   = (const float*)d_in[3];
    const float* w_hh   = (const float*)d_in[4];
    const float* b_ih   = (const float*)d_in[5];
    const float* b_hh   = (const float*)d_in[6];
    const float* w1     = (const float*)d_in[7];
    const float* b1     = (const float*)d_in[8];
    const float* w2     = (const float*)d_in[9];
    const float* b2     = (const float*)d_in[10];
    const float* wp     = (const float*)d_in[11];
    const float* bp     = (const float*)d_in[12];
    float* out = (float*)d_out;

    float *xw, *hidden, *pre, *td, *hbuf;
    cudaGetSymbolAddress((void**)&xw,     g_xw);
    cudaGetSymbolAddress((void**)&hidden, g_hidden);
    cudaGetSymbolAddress((void**)&pre,    g_pre);
    cudaGetSymbolAddress((void**)&td,     g_td);
    cudaGetSymbolAddress((void**)&hbuf,   g_h);

    // td precompute (independent)
    td_kernel<<<255, 256>>>(x, td);

    // xw = x @ w_ih^T + b_ih   : M=65536, N=1536, K=129
    gemm128<0><<<dim3(G3H / 128, (T_DIM * B_DIM) / 128), 256>>>(
        x, w_ih, xw, T_DIM * B_DIM, G3H, D_DIM + 1,
        D_DIM + 1, D_DIM + 1, G3H, b_ih, nullptr, nullptr, nullptr);

    // GRU recurrence: 256 sequential steps, double-buffered h
    const size_t BH = (size_t)B_DIM * H_DIM;
    for (int t = 0; t < T_DIM; t++) {
        const float* hin = (t == 0) ? h0 : (hbuf + (size_t)(t & 1) * BH);
        float* hout = hbuf + (size_t)((t + 1) & 1) * BH;
        gru_step<<<dim3(16, 8), 128>>>(hin, hout, xw, w_hh, b_hh, lens, hidden, t);
    }
    // final h is in hbuf[0]  (t=255 writes (256&1)=0)

    // pre = sigmoid(hwt[:, :-1] @ w1^T + b1) : M=65280, N=1280, K=512 (+td col fused)
    gemm128<1><<<dim3(K10D / 128, PRE_ROWS / 128), 256>>>(
        hidden, w1, pre, PRE_ROWS, K10D, H_DIM,
        H_DIM, H_DIM + 1, K10D, b1, td, w1 + H_DIM, nullptr);

    // preds = mask(pre @ w2^T + b2) -> d_out : M=65280, N=128, K=1280
    gemm128<2><<<dim3(1, PRE_ROWS / 128), 256>>>(
        pre, w2, out, PRE_ROWS, D_DIM, K10D,
        K10D, K10D, D_DIM, b2, nullptr, nullptr, lens);

    // dist_params + lengths
    tail_kernel<<<B_DIM, 96>>>(hbuf, wp, bp, lens, out);
}

// round 2
// speedup vs baseline: 1.4234x; 1.4234x over previous
#include <cuda_runtime.h>
#include <math.h>
#include <stdint.h>

// ---------------- problem constants ----------------
#define T_DIM 256
#define B_DIM 256
#define D_DIM 128
#define H_DIM 512
#define G3H   1536            // 3*H
#define TM1   255             // T-1
#define K10D  1280            // 10*D
#define PRE_ROWS (B_DIM*TM1)  // 65280
#define PRED_ELEMS (PRE_ROWS*D_DIM)  // 8355840

// persistent GRU geometry
#define NCTA   128            // 32 unit-chunks x 4 batch-groups
#define GTPB   256
#define UPC    16             // units per CTA
#define BPC    64             // batches per CTA
#define CHUNK  64             // k per smem chunk
#define NCHUNK (H_DIM/CHUNK)  // 8
#define GRU_SMEM ((H_DIM*48 + 2*CHUNK*BPC)*4)   // 131072 B

// ---------------- scratch (static device arrays; no cudaMalloc allowed) ------
__device__ float g_xwT[(size_t)T_DIM * G3H * B_DIM];      // [t][col][b]
__device__ float g_hidden[(size_t)T_DIM * B_DIM * H_DIM]; // [t][b][H]
__device__ float g_pre[(size_t)PRE_ROWS * K10D];          // (b,t) major rows
__device__ float g_td[PRE_ROWS];
__device__ float g_hT[2 * H_DIM * B_DIM];                 // [buf][k][b]
__device__ unsigned g_bar[260];                           // grid barrier counters

// ---------------- f32x2 helpers ----------------
typedef unsigned long long ull;
__device__ __forceinline__ ull lds64(unsigned a) {
    ull v; asm("ld.shared.b64 %0, [%1];" : "=l"(v) : "r"(a)); return v;
}
__device__ __forceinline__ ull swap64(ull p) {
    unsigned lo, hi;
    asm("mov.b64 {%0,%1}, %2;" : "=r"(lo), "=r"(hi) : "l"(p));
    ull q; asm("mov.b64 %0, {%1,%2};" : "=l"(q) : "r"(hi), "r"(lo)); return q;
}
__device__ __forceinline__ void fma2(ull& acc, ull a, ull b) {
    asm("fma.rn.f32x2 %0, %1, %2, %0;" : "+l"(acc) : "l"(a), "l"(b));
}
__device__ __forceinline__ void unpack2(ull p, float& lo, float& hi) {
    asm("mov.b64 {%0,%1}, %2;" : "=f"(lo), "=f"(hi) : "l"(p));
}
__device__ __forceinline__ float fsigmoid(float x) {
    return __fdividef(1.f, 1.f + __expf(-x));
}
__device__ __forceinline__ float ftanh(float x) {
    return 1.f - __fdividef(2.f, __expf(2.f * x) + 1.f);
}

// =======================================================================
// Generic 128x128 fp32 GEMM, C = A[M,K] * B[N,K]^T (+ epilogue)
// MODE 0: xw  -> stores TRANSPOSED into xwT[t][col][b], c += bias
// MODE 1: pre -> A rows remapped into hidden[t][b][H] (skip t=255);
//                c = sigmoid(c + td[row]*w1last[col*513] + bias)
// MODE 2: preds -> c = (t < lengths[b]-1) ? c+bias : 0
// =======================================================================
template <int MODE>
__global__ __launch_bounds__(256)
void gemm128(const float* __restrict__ A, const float* __restrict__ B,
             float* __restrict__ C,
             int M, int N, int K, int lda, int ldb, int ldc,
             const float* __restrict__ bias,
             const float* __restrict__ td,
             const float* __restrict__ w1last,
             const int* __restrict__ lengths)
{
    __shared__ __align__(16) float As[8][128];
    __shared__ __align__(16) float Bs[8][128];

    const int tid = threadIdx.x;
    const int row0 = blockIdx.y * 128;
    const int col0 = blockIdx.x * 128;
    const int tx = tid & 15;
    const int ty = tid >> 4;

    int lr[4], lk[4];
    size_t aoff[4], boff[4];
#pragma unroll
    for (int i = 0; i < 4; i++) {
        int lin = tid + i * 256;
        lr[i] = lin >> 3;
        lk[i] = lin & 7;
        int grow = row0 + lr[i];
        int arow = grow;
        if (MODE == 1) {               // row=(b,t) t<255 -> hidden[t][b]
            int b_ = grow / 255;
            int t_ = grow - b_ * 255;
            arow = t_ * 256 + b_;
        }
        aoff[i] = (size_t)arow * lda + lk[i];
        boff[i] = (size_t)(col0 + lr[i]) * ldb + lk[i];
    }

    float acc[8][8];
#pragma unroll
    for (int i = 0; i < 8; i++)
#pragma unroll
        for (int j = 0; j < 8; j++) acc[i][j] = 0.f;

    for (int k0 = 0; k0 < K; k0 += 8) {
#pragma unroll
        for (int i = 0; i < 4; i++) {
            int gk = k0 + lk[i];
            As[lk[i]][lr[i]] = (gk < K) ? A[aoff[i] + k0] : 0.f;
            Bs[lk[i]][lr[i]] = (gk < K) ? B[boff[i] + k0] : 0.f;
        }
        __syncthreads();
#pragma unroll
        for (int kk = 0; kk < 8; kk++) {
            float ar[8], br[8];
            *(float4*)&ar[0] = *(const float4*)&As[kk][ty * 8];
            *(float4*)&ar[4] = *(const float4*)&As[kk][ty * 8 + 4];
            *(float4*)&br[0] = *(const float4*)&Bs[kk][tx * 8];
            *(float4*)&br[4] = *(const float4*)&Bs[kk][tx * 8 + 4];
#pragma unroll
            for (int i = 0; i < 8; i++)
#pragma unroll
                for (int j = 0; j < 8; j++) acc[i][j] += ar[i] * br[j];
        }
        __syncthreads();
    }

    if (MODE == 0) {
        // transposed store: C[t][col][b], 128-row tile = fixed t, b range
        int tt = row0 >> 8;
        int b0 = (row0 & 255) + ty * 8;
#pragma unroll
        for (int j = 0; j < 8; j++) {
            int gcol = col0 + tx * 8 + j;
            float bz = bias[gcol];
            float4 v0 = make_float4(acc[0][j] + bz, acc[1][j] + bz,
                                    acc[2][j] + bz, acc[3][j] + bz);
            float4 v1 = make_float4(acc[4][j] + bz, acc[5][j] + bz,
                                    acc[6][j] + bz, acc[7][j] + bz);
            size_t base = ((size_t)tt * G3H + gcol) * B_DIM + b0;
            *(float4*)(C + base) = v0;
            *(float4*)(C + base + 4) = v1;
        }
        return;
    }

#pragma unroll
    for (int i = 0; i < 8; i++) {
        int grow = row0 + ty * 8 + i;
        float tdv = 0.f;
        int b_ = 0, t_ = 0;
        if (MODE == 1) tdv = td[grow];
        if (MODE == 2) { b_ = grow / 255; t_ = grow - b_ * 255; }
#pragma unroll
        for (int j = 0; j < 8; j++) {
            int gcol = col0 + tx * 8 + j;
            float v = acc[i][j];
            if (MODE == 1) {
                v += bias[gcol] + tdv * w1last[(size_t)gcol * 513];
                v = 1.f / (1.f + expf(-v));
            } else { // MODE 2
                v = (t_ < lengths[b_] - 1) ? (v + bias[gcol]) : 0.f;
            }
            C[(size_t)grow * ldc + gcol] = v;
        }
    }
}

// =======================================================================
// Persistent GRU: 128 CTAs resident (1/SM), all 256 steps in one launch.
// CTA (jc,bgi): 16 units x 3 gates x 64 batches. w slice in SMEM for the
// whole kernel. h in global transposed hT[buf][k][b], grid barrier per step.
// =======================================================================
__global__ __launch_bounds__(GTPB, 1)
void gru_persistent(const float* __restrict__ h0,
                    const float* __restrict__ xwT,
                    const float* __restrict__ w_hh,
                    const float* __restrict__ b_hh,
                    const int*   __restrict__ lengths,
                    float* __restrict__ hT,
                    float* __restrict__ hidden,
                    unsigned* __restrict__ bar)
{
    extern __shared__ float sm[];
    float* w_s = sm;                       // [512][48]
    float* h_s = sm + H_DIM * 48;          // [2][64][64]

    const int tid = threadIdx.x;
    const int jc  = blockIdx.x & 31;
    const int bgi = blockIdx.x >> 5;
    const int ubase = jc * UPC;
    const int bbase = bgi * BPC;
    const int ut = tid >> 5;               // 0..7
    const int bt = tid & 31;               // 0..31
    const int u0 = ut * 2;
    const int b0 = bt * 2;

    unsigned sm_base;
    asm("{.reg .u64 t0; cvta.to.shared.u64 t0, %1; cvt.u32.u64 %0, t0;}"
        : "=r"(sm_base) : "l"(sm));
    const unsigned sw_w = sm_base;
    const unsigned sw_h = sm_base + H_DIM * 48 * 4;

    // ---- one-time: load w slice (48 rows x 512) transposed into w_s[k][row]
    for (int i = tid; i < 48 * 128; i += GTPB) {
        int r = i >> 7, kq = i & 127;
        int g = r >> 4, u = r & 15;
        float4 w4 = *(const float4*)(w_hh + (size_t)(g * H_DIM + ubase + u) * H_DIM + kq * 4);
        int col = g * 16 + u;
        w_s[(kq * 4 + 0) * 48 + col] = w4.x;
        w_s[(kq * 4 + 1) * 48 + col] = w4.y;
        w_s[(kq * 4 + 2) * 48 + col] = w4.z;
        w_s[(kq * 4 + 3) * 48 + col] = w4.w;
    }
    // ---- one-time: transpose own tile of h0 into hT[0]
    for (int i = tid; i < UPC * BPC; i += GTPB) {
        int u = i >> 6, b = i & 63;
        hT[(size_t)(ubase + u) * B_DIM + bbase + b] =
            h0[(size_t)(bbase + b) * H_DIM + ubase + u];
    }
    // grid barrier 0
    __syncthreads();
    if (tid == 0) {
        __threadfence();
        atomicAdd(&bar[0], 1u);
        volatile unsigned* f = &bar[0];
        while (*f < (unsigned)NCTA) __nanosleep(64);
    }
    __syncthreads();

    // per-thread loop-invariant values
    float bh[3][2];
#pragma unroll
    for (int g = 0; g < 3; g++) {
        bh[g][0] = b_hh[g * H_DIM + ubase + u0];
        bh[g][1] = b_hh[g * H_DIM + ubase + u0 + 1];
    }
    const int len0 = lengths[bbase + b0];
    const int len1 = lengths[bbase + b0 + 1];

    const unsigned hoff = b0 * 4;
    const unsigned woff = u0 * 4;

    for (int t = 0; t < T_DIM; t++) {
        const float* hcur = hT + (size_t)(t & 1) * H_DIM * B_DIM;
        float*       hnxt = hT + (size_t)((t + 1) & 1) * H_DIM * B_DIM;

        ull accd0 = 0, accd1 = 0, accd2 = 0;
        ull accc0 = 0, accc1 = 0, accc2 = 0;

        // prefetch chunk 0
        float4 pf[4];
#pragma unroll
        for (int i = 0; i < 4; i++) {
            int q = tid + i * GTPB;
            int k = q >> 4, bq = q & 15;
            pf[i] = __ldcg((const float4*)(hcur + (size_t)k * B_DIM + bbase + bq * 4));
        }

        for (int c = 0; c < NCHUNK; c++) {
            __syncthreads();            // prev compute done before overwrite
#pragma unroll
            for (int i = 0; i < 4; i++) {
                int q = tid + i * GTPB;
                int k = q >> 4, bq = q & 15;
                *(float4*)(h_s + (c & 1) * (CHUNK * BPC) + k * BPC + bq * 4) = pf[i];
            }
            if (c < NCHUNK - 1) {
#pragma unroll
                for (int i = 0; i < 4; i++) {
                    int q = tid + i * GTPB;
                    int k = q >> 4, bq = q & 15;
                    pf[i] = __ldcg((const float4*)(hcur + (size_t)((c + 1) * CHUNK + k) * B_DIM + bbase + bq * 4));
                }
            }
            __syncthreads();

            const unsigned hbase = sw_h + (c & 1) * (CHUNK * BPC * 4) + hoff;
            const unsigned wbase = sw_w + (c * CHUNK) * 192 + woff;
#pragma unroll 32
            for (int kk = 0; kk < CHUNK; kk++) {
                ull h2  = lds64(hbase + kk * 256);
                ull h2s = swap64(h2);
                ull w0  = lds64(wbase + kk * 192);
                ull w1  = lds64(wbase + kk * 192 + 64);
                ull w2  = lds64(wbase + kk * 192 + 128);
                fma2(accd0, w0, h2);  fma2(accc0, w0, h2s);
                fma2(accd1, w1, h2);  fma2(accc1, w1, h2s);
                fma2(accd2, w2, h2);  fma2(accc2, w2, h2s);
            }
        }

        // ---- epilogue: 4 combos (u0/u1 x b0/b1)
        // accd = (u0b0, u1b1), accc = (u0b1, u1b0)
        float A0[4], A1[4], A2[4];
        unpack2(accd0, A0[0], A0[3]); unpack2(accc0, A0[1], A0[2]);
        unpack2(accd1, A1[0], A1[3]); unpack2(accc1, A1[1], A1[2]);
        unpack2(accd2, A2[0], A2[3]); unpack2(accc2, A2[1], A2[2]);

#pragma unroll
        for (int cb = 0; cb < 4; cb++) {
            const int du = cb >> 1, db = cb & 1;
            const int uu = ubase + u0 + du;
            const int bb = bbase + b0 + db;
            const size_t xbase = ((size_t)t * G3H + uu) * B_DIM + bb;
            float xr = __ldg(xwT + xbase);
            float xz = __ldg(xwT + xbase + (size_t)H_DIM * B_DIM);
            float xn = __ldg(xwT + xbase + (size_t)2 * H_DIM * B_DIM);
            float hold = __ldcg(hcur + (size_t)uu * B_DIM + bb);
            float r = fsigmoid(xr + A0[cb] + bh[0][du]);
            float z = fsigmoid(xz + A1[cb] + bh[1][du]);
            float n = ftanh(xn + r * (A2[cb] + bh[2][du]));
            float hnew = (1.f - z) * n + z * hold;
            bool valid = t < ((db == 0) ? len0 : len1);
            hnxt[(size_t)uu * B_DIM + bb] = valid ? hnew : hold;
            hidden[((size_t)t * B_DIM + bb) * H_DIM + uu] = valid ? hnew : 0.f;
        }

        // ---- grid barrier for step t
        __syncthreads();
        if (tid == 0) {
            __threadfence();
            atomicAdd(&bar[t + 1], 1u);
            volatile unsigned* f = &bar[t + 1];
            while (*f < (unsigned)NCTA) __nanosleep(64);
        }
        __syncthreads();
    }
}

// =======================================================================
// td[b,t] = x[t+1,b,0] - x[t,b,0]
// =======================================================================
__global__ void td_kernel(const float* __restrict__ x, float* __restrict__ td)
{
    int i = blockIdx.x * 256 + threadIdx.x;
    if (i < PRE_ROWS) {
        int b = i / 255;
        int t = i - b * 255;
        td[i] = x[(size_t)((t + 1) * B_DIM + b) * (D_DIM + 1)]
              - x[(size_t)(t * B_DIM + b) * (D_DIM + 1)];
    }
}

// =======================================================================
// dist_params + lengths; hlast is transposed hT[0]: [k][b]
// =======================================================================
__global__ void tail_kernel(const float* __restrict__ hT0,
                            const float* __restrict__ wp,
                            const float* __restrict__ bp,
                            const int* __restrict__ lengths,
                            float* __restrict__ out)
{
    int b = blockIdx.x;
    int w = threadIdx.x >> 5;
    int lane = threadIdx.x & 31;
    float s = 0.f;
    for (int k = lane; k < H_DIM; k += 32)
        s += hT0[(size_t)k * B_DIM + b] * wp[(size_t)w * H_DIM + k];
#pragma unroll
    for (int o = 16; o; o >>= 1) s += __shfl_xor_sync(0xffffffffu, s, o);
    if (lane == 0)
        out[PRED_ELEMS + b * 3 + w] = expf(-(s + bp[w]));
    if (threadIdx.x == 0)
        out[PRED_ELEMS + B_DIM * 3 + b] = (float)lengths[b];
}

// =======================================================================
// host launcher
// =======================================================================
extern "C" void kernel_launch(void* const* d_in, const int* in_sizes, int n_in,
                              void* d_out, int out_size)
{
    const float* x    = (const float*)d_in[0];
    const float* h0   = (const float*)d_in[1];
    const int*   lens = (const int*)  d_in[2];
    const float* w_ih = (const float*)d_in[3];
    const float* w_hh = (const float*)d_in[4];
    const float* b_ih = (const float*)d_in[5];
    const float* b_hh = (const float*)d_in[6];
    const float* w1   = (const float*)d_in[7];
    const float* b1   = (const float*)d_in[8];
    const float* w2   = (const float*)d_in[9];
    const float* b2   = (const float*)d_in[10];
    const float* wp   = (const float*)d_in[11];
    const float* bp   = (const float*)d_in[12];
    float* out = (float*)d_out;

    float *xwT, *hidden, *pre, *td, *hT;
    unsigned* bar;
    cudaGetSymbolAddress((void**)&xwT,    g_xwT);
    cudaGetSymbolAddress((void**)&hidden, g_hidden);
    cudaGetSymbolAddress((void**)&pre,    g_pre);
    cudaGetSymbolAddress((void**)&td,     g_td);
    cudaGetSymbolAddress((void**)&hT,     g_hT);
    cudaGetSymbolAddress((void**)&bar,    g_bar);

    cudaFuncSetAttribute(gru_persistent,
                         cudaFuncAttributeMaxDynamicSharedMemorySize, GRU_SMEM);

    // reset grid-barrier counters (memset node -> reset on every graph replay)
    cudaMemsetAsync(bar, 0, 260 * sizeof(unsigned));

    td_kernel<<<255, 256>>>(x, td);

    // xwT[t][col][b] = (x @ w_ih^T + b_ih) transposed
    gemm128<0><<<dim3(G3H / 128, (T_DIM * B_DIM) / 128), 256>>>(
        x, w_ih, xwT, T_DIM * B_DIM, G3H, D_DIM + 1,
        D_DIM + 1, D_DIM + 1, G3H, b_ih, nullptr, nullptr, nullptr);

    // persistent GRU (all 256 steps)
    gru_persistent<<<NCTA, GTPB, GRU_SMEM>>>(h0, xwT, w_hh, b_hh, lens,
                                             hT, hidden, bar);

    // pre = sigmoid(hwt[:, :-1] @ w1^T + b1), td column fused
    gemm128<1><<<dim3(K10D / 128, PRE_ROWS / 128), 256>>>(
        hidden, w1, pre, PRE_ROWS, K10D, H_DIM,
        H_DIM, H_DIM + 1, K10D, b1, td, w1 + H_DIM, nullptr);

    // preds = mask(pre @ w2^T + b2) -> d_out
    gemm128<2><<<dim3(1, PRE_ROWS / 128), 256>>>(
        pre, w2, out, PRE_ROWS, D_DIM, K10D,
        K10D, K10D, D_DIM, b2, nullptr, nullptr, lens);

    // dist_params + lengths (final h is hT buffer 0 after 256 steps)
    tail_kernel<<<B_DIM, 96>>>(hT, wp, bp, lens, out);
}